// round 11
// baseline (speedup 1.0000x reference)
#include <cuda_runtime.h>

// Problem constants (from reference: N=10000, C=128, E=640000, H=8)
#define C_DIM 128
#define H_DIM 8
#define NPB 64              // nodes per proj block (4 groups of 16)
#define MAX_N 10000
#define WT_PITCH 132        // padded: bank4(k*132+4j) = (k+j) mod 32, conflict-free
#define TPB 256

// Scratch: per-node projections. y[n*16 + h]     = x[n]·Wr[:,h] + b[h]   (h<8)
//                                y[n*16 + 8 + h] = x[n]·Wc[:,h]          (h<8)
__device__ float g_y[(size_t)MAX_N * 16];

__device__ __forceinline__ float fast_sigmoid(float l, float attr)
{
    // sigmoid(l) = 0.5*tanh(0.5*l) + 0.5   (MUFU.TANH, sm_75+)
    float t;
    asm("tanh.approx.f32 %0, %1;" : "=f"(t) : "f"(0.5f * l));
    return attr * fmaf(t, 0.5f, 0.5f);
}

// ---------------------------------------------------------------------------
// Kernel A (primary): node projection. 256 threads, 64-node tile, W
// transposed once into padded shared (conflict-free float4 reads).
// Fires the PDL trigger immediately so the edge kernel's prologue overlaps.
// ---------------------------------------------------------------------------
__global__ void __launch_bounds__(TPB) node_proj_kernel(
    const float* __restrict__ x,
    const float* __restrict__ W,   // (2C, H) row-major
    const float* __restrict__ b,   // (H,)
    int N)
{
#if __CUDA_ARCH__ >= 900
    cudaTriggerProgrammaticLaunchCompletion();
#endif

    __shared__ float sWt[16 * WT_PITCH];              // ~8.4 KB
    __shared__ float sX[NPB * C_DIM];                 // 32 KB

    const int tid = threadIdx.x;
    const int nb = blockIdx.x * NPB;

    // Load + transpose W into padded layout (once per block).
    #pragma unroll
    for (int i = 0; i < 8; i++) {
        int idx = tid + i * 256;              // 0..2047
        int row = idx >> 3;
        int h = idx & 7;
        int k = h + ((row >= C_DIM) ? H_DIM : 0);
        int c = row & (C_DIM - 1);
        sWt[k * WT_PITCH + c] = W[idx];
    }

    // Load 64x128 x tile as float4.
    {
        const float4* x4 = reinterpret_cast<const float4*>(x);
        float4* sX4 = reinterpret_cast<float4*>(sX);
        #pragma unroll
        for (int i = 0; i < 8; i++) {
            int idx = tid + i * 256;               // float4 index in tile
            int n = nb + (idx >> 5);               // 32 float4 per row
            sX4[idx] = (n < N) ? x4[(size_t)n * 32 + (idx & 31)]
                               : make_float4(0.f, 0.f, 0.f, 0.f);
        }
    }
    __syncthreads();

    const int local_n0 = tid >> 4;   // 0..15
    const int k = tid & 15;          // 0..15 (0..7 -> Wr+b, 8..15 -> Wc)
    const float4* w4 = reinterpret_cast<const float4*>(&sWt[k * WT_PITCH]);
    const float bias = (k < H_DIM) ? b[k] : 0.0f;

    #pragma unroll
    for (int g = 0; g < NPB / 16; g++) {
        const int local_n = g * 16 + local_n0;
        const int n = nb + local_n;
        const float4* xr4 = reinterpret_cast<const float4*>(&sX[local_n * C_DIM]);

        float acc = bias;
        #pragma unroll
        for (int j = 0; j < C_DIM / 4; j++) {
            float4 xv = xr4[j];
            float4 wv = w4[j];
            acc = fmaf(xv.x, wv.x, acc);
            acc = fmaf(xv.y, wv.y, acc);
            acc = fmaf(xv.z, wv.z, acc);
            acc = fmaf(xv.w, wv.w, acc);
        }
        if (n < N)
            g_y[(size_t)n * 16 + k] = acc;
    }
}

// ---------------------------------------------------------------------------
// Kernel B (secondary): 2 threads per edge, one float4 (4 heads) each.
// Prologue (index/attr loads, local dtype probe, tail index writes) does not
// depend on g_y; with PDL it overlaps node_proj, without PDL it's just the
// same code run after node_proj completes (stream order).
// mode: 0 = alpha only, 1 = float-cast idx tail, 2 = raw int64 idx tail.
// ---------------------------------------------------------------------------
__global__ void __launch_bounds__(TPB) edge_kernel_h4(
    const void* __restrict__ ei_raw,
    const float* __restrict__ ea,
    float* __restrict__ out,
    int E, int N, int mode)
{
    const int t = blockIdx.x * blockDim.x + threadIdx.x;
    const bool active = (t < E * 2);

    // Local dtype probe: 4 broadcast 64-bit loads (L1-cached). Genuine int64
    // ids all lie in [0, N); int32 data read as int64 fuses two ids and the
    // fused value exceeds N unless 4 odd-position ids are all zero (~1e-16).
    const long long* p64 = (const long long*)ei_raw;
    const long long w0 = __ldg(p64 + 0), w1 = __ldg(p64 + 1);
    const long long w2 = __ldg(p64 + 2), w3 = __ldg(p64 + 3);
    const unsigned long long nn = (unsigned long long)N;
    const bool is64 = ((unsigned long long)w0 < nn) & ((unsigned long long)w1 < nn)
                    & ((unsigned long long)w2 < nn) & ((unsigned long long)w3 < nn);

    int e = 0, half = 0;
    long long r64 = 0, c64 = 0;
    float attr = 0.0f;

    if (active) {
        e = t >> 1;
        half = t & 1;

        if (is64) {
            const long long* ei = (const long long*)ei_raw;
            r64 = __ldg(&ei[e]);
            c64 = __ldg(&ei[(size_t)E + e]);
        } else {
            const int* ei = (const int*)ei_raw;
            r64 = __ldg(&ei[e]);
            c64 = __ldg(&ei[(size_t)E + e]);
        }
        attr = __ldg(&ea[e]);

        // Tail index writes don't depend on g_y: do them pre-sync.
        if (mode == 1) {
            float* tf = out + (size_t)E * H_DIM;
            if (half == 0) tf[e] = (float)r64;
            else           tf[(size_t)E + e] = (float)c64;
        } else if (mode == 2) {
            long long* t64o = (long long*)(out + (size_t)E * H_DIM);
            if (half == 0) t64o[e] = r64;
            else           t64o[(size_t)E + e] = c64;
        }
    }

#if __CUDA_ARCH__ >= 900
    cudaGridDependencySynchronize();   // waits for primary grid's g_y stores
#endif

    if (!active) return;

    // Unsigned clamp: negatives wrap to huge and get clamped too.
    const unsigned ri = min((unsigned)r64, (unsigned)(MAX_N - 1));
    const unsigned ci = min((unsigned)c64, (unsigned)(MAX_N - 1));

    const float4 yr = *reinterpret_cast<const float4*>(g_y + ri * 16u + 4u * half);
    const float4 yc = *reinterpret_cast<const float4*>(g_y + ci * 16u + 8u + 4u * half);

    const bool sl = (r64 == c64);

    float4 res;
    res.x = sl ? 1.0f : fast_sigmoid(yr.x + yc.x, attr);
    res.y = sl ? 1.0f : fast_sigmoid(yr.y + yc.y, attr);
    res.z = sl ? 1.0f : fast_sigmoid(yr.z + yc.z, attr);
    res.w = sl ? 1.0f : fast_sigmoid(yr.w + yc.w, attr);

    // out[e*8 + 4*half .. +3] == ((float4*)out)[t] : perfectly coalesced.
    reinterpret_cast<float4*>(out)[t] = res;
}

// ---------------------------------------------------------------------------
extern "C" void kernel_launch(void* const* d_in, const int* in_sizes, int n_in,
                              void* d_out, int out_size)
{
    const float* x  = (const float*)d_in[0];   // (N, 128)
    const void*  ei = d_in[1];                 // (2, E) int32 or int64
    const float* ea = (const float*)d_in[2];   // (E,)
    const float* W  = (const float*)d_in[3];   // (256, 8)
    const float* b  = (const float*)d_in[4];   // (8,)

    const int N = in_sizes[0] / C_DIM;
    const int E = in_sizes[2];
    float* out = (float*)d_out;

    const long long extra = (long long)out_size - (long long)E * H_DIM;
    int mode = 0;
    if (extra == 2LL * E) mode = 1;       // indices cast to float
    else if (extra == 4LL * E) mode = 2;  // raw int64 indices appended

    // Primary: node projection.
    node_proj_kernel<<<(N + NPB - 1) / NPB, TPB>>>(x, W, b, N);

    // Secondary: edge kernel. Try PDL overlap; on ANY error fall back to a
    // plain stream-ordered launch of the same kernel (identical semantics).
    const int total = E * 2;
    const dim3 egrid((total + TPB - 1) / TPB, 1, 1);

    cudaLaunchConfig_t cfg = {};
    cfg.gridDim = egrid;
    cfg.blockDim = dim3(TPB, 1, 1);
    cfg.dynamicSmemBytes = 0;
    cfg.stream = 0;
    cudaLaunchAttribute attrs[1];
    attrs[0].id = cudaLaunchAttributeProgrammaticStreamSerialization;
    attrs[0].val.programmaticStreamSerializationAllowed = 1;
    cfg.attrs = attrs;
    cfg.numAttrs = 1;

    cudaError_t st = cudaLaunchKernelEx(&cfg, edge_kernel_h4,
                                        ei, ea, out, E, N, mode);
    if (st != cudaSuccess) {
        (void)cudaGetLastError();   // clear sticky error state
        edge_kernel_h4<<<egrid, TPB>>>(ei, ea, out, E, N, mode);
    }
}

// round 12
// speedup vs baseline: 1.0281x; 1.0281x over previous
#include <cuda_runtime.h>

// Problem constants (from reference: N=10000, C=128, E=640000, H=8)
#define C_DIM 128
#define H_DIM 8
#define NPB 64              // nodes per proj block (4 groups of 16)
#define MAX_N 10000
#define WT_PITCH 132        // padded: bank4(k*132+4j) = (k+j) mod 32, conflict-free
#define TPB 256

// Scratch: per-node projections. y[n*16 + h]     = x[n]·Wr[:,h] + b[h]   (h<8)
//                                y[n*16 + 8 + h] = x[n]·Wc[:,h]          (h<8)
__device__ float g_y[(size_t)MAX_N * 16];

__device__ __forceinline__ float fast_sigmoid(float l, float attr)
{
    // sigmoid(l) = 0.5*tanh(0.5*l) + 0.5   (MUFU.TANH, sm_75+)
    float t;
    asm("tanh.approx.f32 %0, %1;" : "=f"(t) : "f"(0.5f * l));
    return attr * fmaf(t, 0.5f, 0.5f);
}

// ---------------------------------------------------------------------------
// Kernel A (primary): node projection. 256 threads, 64-node tile, W
// transposed once into padded shared (conflict-free float4 reads).
// Fires the PDL trigger immediately so the edge kernel's prologue overlaps.
// ---------------------------------------------------------------------------
__global__ void __launch_bounds__(TPB) node_proj_kernel(
    const float* __restrict__ x,
    const float* __restrict__ W,   // (2C, H) row-major
    const float* __restrict__ b,   // (H,)
    int N)
{
#if __CUDA_ARCH__ >= 900
    cudaTriggerProgrammaticLaunchCompletion();
#endif

    __shared__ float sWt[16 * WT_PITCH];              // ~8.4 KB
    __shared__ float sX[NPB * C_DIM];                 // 32 KB

    const int tid = threadIdx.x;
    const int nb = blockIdx.x * NPB;

    // Load + transpose W into padded layout (once per block).
    #pragma unroll
    for (int i = 0; i < 8; i++) {
        int idx = tid + i * 256;              // 0..2047
        int row = idx >> 3;
        int h = idx & 7;
        int k = h + ((row >= C_DIM) ? H_DIM : 0);
        int c = row & (C_DIM - 1);
        sWt[k * WT_PITCH + c] = W[idx];
    }

    // Load 64x128 x tile as float4.
    {
        const float4* x4 = reinterpret_cast<const float4*>(x);
        float4* sX4 = reinterpret_cast<float4*>(sX);
        #pragma unroll
        for (int i = 0; i < 8; i++) {
            int idx = tid + i * 256;               // float4 index in tile
            int n = nb + (idx >> 5);               // 32 float4 per row
            sX4[idx] = (n < N) ? x4[(size_t)n * 32 + (idx & 31)]
                               : make_float4(0.f, 0.f, 0.f, 0.f);
        }
    }
    __syncthreads();

    const int local_n0 = tid >> 4;   // 0..15
    const int k = tid & 15;          // 0..15 (0..7 -> Wr+b, 8..15 -> Wc)
    const float4* w4 = reinterpret_cast<const float4*>(&sWt[k * WT_PITCH]);
    const float bias = (k < H_DIM) ? b[k] : 0.0f;

    #pragma unroll
    for (int g = 0; g < NPB / 16; g++) {
        const int local_n = g * 16 + local_n0;
        const int n = nb + local_n;
        const float4* xr4 = reinterpret_cast<const float4*>(&sX[local_n * C_DIM]);

        float acc = bias;
        #pragma unroll
        for (int j = 0; j < C_DIM / 4; j++) {
            float4 xv = xr4[j];
            float4 wv = w4[j];
            acc = fmaf(xv.x, wv.x, acc);
            acc = fmaf(xv.y, wv.y, acc);
            acc = fmaf(xv.z, wv.z, acc);
            acc = fmaf(xv.w, wv.w, acc);
        }
        if (n < N)
            g_y[(size_t)n * 16 + k] = acc;
    }
}

// ---------------------------------------------------------------------------
// Kernel B (secondary): 2 threads per edge, one float4 (4 heads) each.
// Prologue (index/attr loads, local dtype probe, tail index writes) does not
// depend on g_y; with PDL it overlaps node_proj, without PDL it's just the
// same code run after node_proj completes (stream order).
// mode: 0 = alpha only, 1 = float-cast idx tail, 2 = raw int64 idx tail.
// ---------------------------------------------------------------------------
__global__ void __launch_bounds__(TPB) edge_kernel_h4(
    const void* __restrict__ ei_raw,
    const float* __restrict__ ea,
    float* __restrict__ out,
    int E, int N, int mode)
{
    const int t = blockIdx.x * blockDim.x + threadIdx.x;
    const bool active = (t < E * 2);

    // Local dtype probe: 4 broadcast 64-bit loads (L1-cached). Genuine int64
    // ids all lie in [0, N); int32 data read as int64 fuses two ids and the
    // fused value exceeds N unless 4 odd-position ids are all zero (~1e-16).
    const long long* p64 = (const long long*)ei_raw;
    const long long w0 = __ldg(p64 + 0), w1 = __ldg(p64 + 1);
    const long long w2 = __ldg(p64 + 2), w3 = __ldg(p64 + 3);
    const unsigned long long nn = (unsigned long long)N;
    const bool is64 = ((unsigned long long)w0 < nn) & ((unsigned long long)w1 < nn)
                    & ((unsigned long long)w2 < nn) & ((unsigned long long)w3 < nn);

    int e = 0, half = 0;
    long long r64 = 0, c64 = 0;
    float attr = 0.0f;

    if (active) {
        e = t >> 1;
        half = t & 1;

        if (is64) {
            const long long* ei = (const long long*)ei_raw;
            r64 = __ldg(&ei[e]);
            c64 = __ldg(&ei[(size_t)E + e]);
        } else {
            const int* ei = (const int*)ei_raw;
            r64 = __ldg(&ei[e]);
            c64 = __ldg(&ei[(size_t)E + e]);
        }
        attr = __ldg(&ea[e]);

        // Tail index writes don't depend on g_y: do them pre-sync.
        if (mode == 1) {
            float* tf = out + (size_t)E * H_DIM;
            if (half == 0) tf[e] = (float)r64;
            else           tf[(size_t)E + e] = (float)c64;
        } else if (mode == 2) {
            long long* t64o = (long long*)(out + (size_t)E * H_DIM);
            if (half == 0) t64o[e] = r64;
            else           t64o[(size_t)E + e] = c64;
        }
    }

#if __CUDA_ARCH__ >= 900
    cudaGridDependencySynchronize();   // waits for primary grid's g_y stores
#endif

    if (!active) return;

    // Unsigned clamp: negatives wrap to huge and get clamped too.
    const unsigned ri = min((unsigned)r64, (unsigned)(MAX_N - 1));
    const unsigned ci = min((unsigned)c64, (unsigned)(MAX_N - 1));

    const float4 yr = *reinterpret_cast<const float4*>(g_y + ri * 16u + 4u * half);
    const float4 yc = *reinterpret_cast<const float4*>(g_y + ci * 16u + 8u + 4u * half);

    const bool sl = (r64 == c64);

    float4 res;
    res.x = sl ? 1.0f : fast_sigmoid(yr.x + yc.x, attr);
    res.y = sl ? 1.0f : fast_sigmoid(yr.y + yc.y, attr);
    res.z = sl ? 1.0f : fast_sigmoid(yr.z + yc.z, attr);
    res.w = sl ? 1.0f : fast_sigmoid(yr.w + yc.w, attr);

    // out[e*8 + 4*half .. +3] == ((float4*)out)[t] : perfectly coalesced.
    reinterpret_cast<float4*>(out)[t] = res;
}

// ---------------------------------------------------------------------------
extern "C" void kernel_launch(void* const* d_in, const int* in_sizes, int n_in,
                              void* d_out, int out_size)
{
    const float* x  = (const float*)d_in[0];   // (N, 128)
    const void*  ei = d_in[1];                 // (2, E) int32 or int64
    const float* ea = (const float*)d_in[2];   // (E,)
    const float* W  = (const float*)d_in[3];   // (256, 8)
    const float* b  = (const float*)d_in[4];   // (8,)

    const int N = in_sizes[0] / C_DIM;
    const int E = in_sizes[2];
    float* out = (float*)d_out;

    const long long extra = (long long)out_size - (long long)E * H_DIM;
    int mode = 0;
    if (extra == 2LL * E) mode = 1;       // indices cast to float
    else if (extra == 4LL * E) mode = 2;  // raw int64 indices appended

    // Primary: node projection.
    node_proj_kernel<<<(N + NPB - 1) / NPB, TPB>>>(x, W, b, N);

    // Secondary: edge kernel. Try PDL overlap; on ANY error fall back to a
    // plain stream-ordered launch of the same kernel (identical semantics).
    const int total = E * 2;
    const dim3 egrid((total + TPB - 1) / TPB, 1, 1);

    cudaLaunchConfig_t cfg = {};
    cfg.gridDim = egrid;
    cfg.blockDim = dim3(TPB, 1, 1);
    cfg.dynamicSmemBytes = 0;
    cfg.stream = 0;
    cudaLaunchAttribute attrs[1];
    attrs[0].id = cudaLaunchAttributeProgrammaticStreamSerialization;
    attrs[0].val.programmaticStreamSerializationAllowed = 1;
    cfg.attrs = attrs;
    cfg.numAttrs = 1;

    cudaError_t st = cudaLaunchKernelEx(&cfg, edge_kernel_h4,
                                        ei, ea, out, E, N, mode);
    if (st != cudaSuccess) {
        (void)cudaGetLastError();   // clear sticky error state
        edge_kernel_h4<<<egrid, TPB>>>(ei, ea, out, E, N, mode);
    }
}